// round 9
// baseline (speedup 1.0000x reference)
#include <cuda_runtime.h>
#include <math.h>

// ---------------- problem constants ----------------
#define VNUM   6890
#define V3CNT  (VNUM*3)
#define KVP    6912          // V padded to multiple of 64
#define NJ     24
#define NK     19
#define NBETA  10
#define BATCH  1024
#define NXCOL  224           // 218 (1 + 10 beta + 207 pose) padded
#define NUCOL  456           // k*24+j
#define NRCOLP 512           // 480 (456 + 24 Jreg cols) padded
#define MLROWS 655           // 3*218 basis rows + 1 ones row
#define MLROWSP 704
#define N2     1368          // kj*3+c
#define N2P    1408
#define KCHUNK (KVP/4)       // 1728, split-K = 4

// ---------------- scratch (__device__ globals: no allocation) ----------------
__device__ float g_Rbuf[KVP*NRCOLP];        // [v][n]
__device__ float g_Lbuf[MLROWSP*KVP];       // [r][v]
__device__ float g_Cpart[4*NRCOLP*MLROWSP]; // split-K partials [s][n][r]
__device__ float g_Gf[NRCOLP*MLROWSP];      // [n][r]
__device__ float g_CPB[NXCOL*N2P];          // [p][n2]
__device__ float g_W2[NUCOL];
__device__ float g_X[BATCH*NXCOL];
__device__ float g_RsB[BATCH*216];          // 24 rotations x 9
__device__ float g_M[BATCH*N2P];

__constant__ int c_par[24] = {-1,0,0,0,1,2,3,4,5,6,7,8,9,9,9,12,13,14,16,17,18,19,20,21};

// ---------------- pack R: columns = jr[v,k]*w[v,j] (456) ++ Jreg[v,j] (24) ----------------
__global__ void build_R_k(const float* __restrict__ Jreg,
                          const float* __restrict__ jr,
                          const float* __restrict__ w) {
    int idx = blockIdx.x*blockDim.x + threadIdx.x;
    if (idx >= KVP*NRCOLP) return;
    int v = idx / NRCOLP, n = idx % NRCOLP;
    float val = 0.f;
    if (v < VNUM) {
        if (n < NUCOL) {
            int k = n / NJ, j = n % NJ;
            val = jr[v*NK + k] * w[v*NJ + j];
        } else if (n < NUCOL + NJ) {
            val = Jreg[v*NJ + (n - NUCOL)];
        }
    }
    g_Rbuf[idx] = val;
}

// ---------------- pack L: row r = c*218+p -> basis[p, v*3+c]; row 654 = ones ----------------
__global__ void build_L_k(const float* __restrict__ vt,
                          const float* __restrict__ sd,
                          const float* __restrict__ pd) {
    int idx = blockIdx.x*blockDim.x + threadIdx.x;
    if (idx >= MLROWSP*KVP) return;
    int r = idx / KVP, v = idx % KVP;
    float val = 0.f;
    if (v < VNUM) {
        if (r < 654) {
            int c = r / 218, p = r % 218;
            if (p == 0)        val = vt[v*3 + c];
            else if (p <= 10)  val = sd[(p-1)*V3CNT + v*3 + c];
            else               val = pd[(p-11)*V3CNT + v*3 + c];
        } else if (r == 654) {
            val = 1.f;
        }
    }
    g_Lbuf[idx] = val;
}

// ---------------- GEMM1: G[n,r] = sum_v Rbuf[v,n] * Lbuf[r,v]; 64x64 tiles, split-K=4 ----------------
__global__ __launch_bounds__(256) void gemm1_k() {
    __shared__ float As[16][68];   // [v][n]
    __shared__ float Bs[16][68];   // [v][r]
    const int r0 = blockIdx.x * 64;
    const int n0 = blockIdx.y * 64;
    const int kBeg = blockIdx.z * KCHUNK;
    const int tid = threadIdx.x;
    const int tx = tid & 15, ty = tid >> 4;
    const int a_v = tid >> 4, a_n = (tid & 15) * 4;
    const int b_r = tid >> 2, b_v = (tid & 3) * 4;
    float acc[4][4] = {{0.f}};

    for (int kt = 0; kt < KCHUNK; kt += 16) {
        int k0 = kBeg + kt;
        float4 av = *(const float4*)(g_Rbuf + (size_t)(k0 + a_v)*NRCOLP + n0 + a_n);
        float4 bv = *(const float4*)(g_Lbuf + (size_t)(r0 + b_r)*KVP + k0 + b_v);
        *(float4*)&As[a_v][a_n] = av;
        Bs[b_v+0][b_r] = bv.x; Bs[b_v+1][b_r] = bv.y;
        Bs[b_v+2][b_r] = bv.z; Bs[b_v+3][b_r] = bv.w;
        __syncthreads();
        #pragma unroll
        for (int kk = 0; kk < 16; ++kk) {
            float4 a  = *(const float4*)&As[kk][ty*4];
            float4 bq = *(const float4*)&Bs[kk][tx*4];
            acc[0][0] += a.x*bq.x; acc[0][1] += a.x*bq.y; acc[0][2] += a.x*bq.z; acc[0][3] += a.x*bq.w;
            acc[1][0] += a.y*bq.x; acc[1][1] += a.y*bq.y; acc[1][2] += a.y*bq.z; acc[1][3] += a.y*bq.w;
            acc[2][0] += a.z*bq.x; acc[2][1] += a.z*bq.y; acc[2][2] += a.z*bq.z; acc[2][3] += a.z*bq.w;
            acc[3][0] += a.w*bq.x; acc[3][1] += a.w*bq.y; acc[3][2] += a.w*bq.z; acc[3][3] += a.w*bq.w;
        }
        __syncthreads();
    }
    float* C = g_Cpart + (size_t)blockIdx.z * NRCOLP * MLROWSP;
    #pragma unroll
    for (int i = 0; i < 4; ++i) {
        int n = n0 + ty*4 + i;
        #pragma unroll
        for (int j = 0; j < 4; ++j)
            C[(size_t)n*MLROWSP + r0 + tx*4 + j] = acc[i][j];
    }
}

__global__ void reduce_k() {
    int i = blockIdx.x*blockDim.x + threadIdx.x;
    const int sz = NRCOLP*MLROWSP;
    if (i >= sz) return;
    g_Gf[i] = g_Cpart[i] + g_Cpart[i+sz] + g_Cpart[i+2*sz] + g_Cpart[i+3*sz];
}

// ---------------- repack G -> CPB[p][n2], extract W2 ----------------
__global__ void repack_k() {
    int idx = blockIdx.x*blockDim.x + threadIdx.x;
    if (idx < NUCOL) g_W2[idx] = g_Gf[idx*MLROWSP + 654];
    if (idx >= NXCOL*N2P) return;
    int p = idx / N2P, n2 = idx % N2P;
    float val = 0.f;
    if (p < 218 && n2 < N2) {
        int kj = n2 / 3, c = n2 % 3;
        val = g_Gf[kj*MLROWSP + c*218 + p];
    }
    g_CPB[idx] = val;
}

// ---------------- per-batch: Rodrigues + feature vector x[b] ----------------
__global__ void build_X_k(const float* __restrict__ beta, const float* __restrict__ theta) {
    int b = blockIdx.x, t = threadIdx.x;
    float* X = g_X + b*NXCOL;
    if (t < 24) {
        float t0 = theta[b*72 + t*3 + 0];
        float t1 = theta[b*72 + t*3 + 1];
        float t2 = theta[b*72 + t*3 + 2];
        float e0 = t0 + 1e-8f, e1 = t1 + 1e-8f, e2 = t2 + 1e-8f;
        float ang  = sqrtf(e0*e0 + e1*e1 + e2*e2);
        float half = 0.5f * ang;
        float sh = sinf(half), w = cosf(half);
        float inva = 1.0f / ang;
        float x = t0*inva*sh, y = t1*inva*sh, z = t2*inva*sh;
        float qn = rsqrtf(w*w + x*x + y*y + z*z);
        w *= qn; x *= qn; y *= qn; z *= qn;
        float R[9];
        R[0] = 1.f - 2.f*(y*y + z*z); R[1] = 2.f*(x*y - w*z);       R[2] = 2.f*(x*z + w*y);
        R[3] = 2.f*(x*y + w*z);       R[4] = 1.f - 2.f*(x*x + z*z); R[5] = 2.f*(y*z - w*x);
        R[6] = 2.f*(x*z - w*y);       R[7] = 2.f*(y*z + w*x);       R[8] = 1.f - 2.f*(x*x + y*y);
        float* rs = g_RsB + b*216 + t*9;
        #pragma unroll
        for (int e = 0; e < 9; ++e) rs[e] = R[e];
        if (t >= 1) {
            float* xp = X + 11 + (t-1)*9;
            #pragma unroll
            for (int e = 0; e < 9; ++e)
                xp[e] = R[e] - ((e==0 || e==4 || e==8) ? 1.f : 0.f);
        }
    }
    if (t == 31) X[0] = 1.f;
    if (t < 10)  X[1 + t] = beta[b*NBETA + t];
    if (t >= 24 && t < 30) X[218 + (t-24)] = 0.f;
}

// ---------------- GEMM2: M[b][n2] = sum_p X[b][p]*CPB[p][n2] ----------------
__global__ __launch_bounds__(256) void gemm2_k() {
    __shared__ float As[16][68];   // [k][m]
    __shared__ float Bs[16][68];   // [k][n]
    const int n0 = blockIdx.x * 64;
    const int m0 = blockIdx.y * 64;
    const int tid = threadIdx.x;
    const int tx = tid & 15, ty = tid >> 4;
    const int am = tid >> 2, ak = (tid & 3) * 4;
    const int bk = tid >> 4, bn = (tid & 15) * 4;
    float acc[4][4] = {{0.f}};

    for (int k0 = 0; k0 < NXCOL; k0 += 16) {
        float4 av = *(const float4*)(g_X   + (size_t)(m0 + am)*NXCOL + k0 + ak);
        float4 bv = *(const float4*)(g_CPB + (size_t)(k0 + bk)*N2P  + n0 + bn);
        As[ak+0][am] = av.x; As[ak+1][am] = av.y;
        As[ak+2][am] = av.z; As[ak+3][am] = av.w;
        *(float4*)&Bs[bk][bn] = bv;
        __syncthreads();
        #pragma unroll
        for (int kk = 0; kk < 16; ++kk) {
            float4 a  = *(const float4*)&As[kk][ty*4];
            float4 bq = *(const float4*)&Bs[kk][tx*4];
            acc[0][0] += a.x*bq.x; acc[0][1] += a.x*bq.y; acc[0][2] += a.x*bq.z; acc[0][3] += a.x*bq.w;
            acc[1][0] += a.y*bq.x; acc[1][1] += a.y*bq.y; acc[1][2] += a.y*bq.z; acc[1][3] += a.y*bq.w;
            acc[2][0] += a.z*bq.x; acc[2][1] += a.z*bq.y; acc[2][2] += a.z*bq.z; acc[2][3] += a.z*bq.w;
            acc[3][0] += a.w*bq.x; acc[3][1] += a.w*bq.y; acc[3][2] += a.w*bq.z; acc[3][3] += a.w*bq.w;
        }
        __syncthreads();
    }
    #pragma unroll
    for (int i = 0; i < 4; ++i) {
        int m = m0 + ty*4 + i;
        #pragma unroll
        for (int j = 0; j < 4; ++j)
            g_M[(size_t)m*N2P + n0 + tx*4 + j] = acc[i][j];
    }
}

// ---------------- final: J, kinematic chain A, joints ----------------
__global__ void final_k(const float* __restrict__ beta,
                        const float* __restrict__ trans,
                        float* __restrict__ out) {
    __shared__ float sRs[216], sJ[72], sRes[288], sW2[456], sBeta[10], sTr[3];
    int b = blockIdx.x, t = threadIdx.x;  // 128 threads
    for (int i = t; i < 216; i += 128) sRs[i] = g_RsB[b*216 + i];
    for (int i = t; i < 456; i += 128) sW2[i] = g_W2[i];
    if (t < 10) sBeta[t] = beta[b*NBETA + t];
    if (t < 3)  sTr[t]   = trans[b*3 + t];
    __syncthreads();

    // J[j][c] = G[456+j][c*218+0] + sum beta*G[..][c*218+1+nb]
    if (t < 72) {
        int j = t / 3, c = t % 3;
        const float* g = g_Gf + (456 + j)*MLROWSP + c*218;
        float acc = g[0];
        #pragma unroll
        for (int nb = 0; nb < 10; ++nb) acc += sBeta[nb]*g[1 + nb];
        sJ[j*3 + c] = acc;
    }
    __syncthreads();

    // kinematic chain (serial, one thread; 7 blocks/SM hide it)
    if (t == 0) {
        for (int r = 0; r < 3; ++r) {          // root: Rs0 @ diag(1,-1,-1) | J0
            sRes[r*4+0] =  sRs[r*3+0];
            sRes[r*4+1] = -sRs[r*3+1];
            sRes[r*4+2] = -sRs[r*3+2];
            sRes[r*4+3] =  sJ[r];
        }
        for (int i = 1; i < 24; ++i) {
            int p = c_par[i];
            float t0 = sJ[i*3+0] - sJ[p*3+0];
            float t1 = sJ[i*3+1] - sJ[p*3+1];
            float t2 = sJ[i*3+2] - sJ[p*3+2];
            const float* Ri = sRs + i*9;
            const float* rp = sRes + p*12;
            float* ro = sRes + i*12;
            for (int r = 0; r < 3; ++r) {
                float p0 = rp[r*4+0], p1 = rp[r*4+1], p2 = rp[r*4+2], p3 = rp[r*4+3];
                ro[r*4+0] = p0*Ri[0] + p1*Ri[3] + p2*Ri[6];
                ro[r*4+1] = p0*Ri[1] + p1*Ri[4] + p2*Ri[7];
                ro[r*4+2] = p0*Ri[2] + p1*Ri[5] + p2*Ri[8];
                ro[r*4+3] = p0*t0 + p1*t1 + p2*t2 + p3;
            }
        }
    }
    __syncthreads();

    // A[..,3] -= res[..,:3] . J   (each thread touches only its own slot)
    if (t < 72) {
        int j = t / 3, r = t % 3;
        float* ro = sRes + j*12 + r*4;
        float d = ro[0]*sJ[j*3+0] + ro[1]*sJ[j*3+1] + ro[2]*sJ[j*3+2];
        ro[3] -= d;
    }
    __syncthreads();

    // joints[k][r] = trans[r] + sum_j A[j,r,:3].m[k,j,:] + A[j,r,3]*W2[k,j]
    if (t < 57) {
        int k = t / 3, r = t % 3;
        float acc = sTr[r];
        const float* Mb = g_M + (size_t)b*N2P;
        #pragma unroll
        for (int j = 0; j < 24; ++j) {
            int kj = k*24 + j;
            const float* m = Mb + kj*3;
            const float* a = sRes + j*12 + r*4;
            acc += a[0]*m[0] + a[1]*m[1] + a[2]*m[2] + a[3]*sW2[kj];
        }
        out[b*57 + t] = acc;
    }
}

// ---------------- launcher ----------------
extern "C" void kernel_launch(void* const* d_in, const int* in_sizes, int n_in,
                              void* d_out, int out_size) {
    const float* beta  = (const float*)d_in[0];
    const float* theta = (const float*)d_in[1];
    const float* trans = (const float*)d_in[2];
    const float* vt    = (const float*)d_in[3];
    const float* sd    = (const float*)d_in[4];
    const float* Jreg  = (const float*)d_in[5];
    const float* pd    = (const float*)d_in[6];
    const float* jr    = (const float*)d_in[7];
    const float* w     = (const float*)d_in[8];
    float* out = (float*)d_out;

    build_R_k<<<(KVP*NRCOLP + 255)/256, 256>>>(Jreg, jr, w);
    build_L_k<<<(MLROWSP*KVP + 255)/256, 256>>>(vt, sd, pd);
    gemm1_k<<<dim3(MLROWSP/64, NRCOLP/64, 4), 256>>>();
    reduce_k<<<(NRCOLP*MLROWSP + 255)/256, 256>>>();
    repack_k<<<(NXCOL*N2P + 255)/256, 256>>>();
    build_X_k<<<BATCH, 32>>>(beta, theta);
    gemm2_k<<<dim3(N2P/64, BATCH/64), 256>>>();
    final_k<<<BATCH, 128>>>(beta, trans, out);
}

// round 11
// speedup vs baseline: 1.0011x; 1.0011x over previous
#include <cuda_runtime.h>
#include <math.h>

// ---------------- problem constants ----------------
#define VNUM   6890
#define V3CNT  (VNUM*3)
#define KVP    6912          // V padded to multiple of 64
#define NJ     24
#define NK     19
#define NBETA  10
#define BATCH  1024
#define NXCOL  224           // 218 (1 + 10 beta + 207 pose) padded
#define NUCOL  456           // k*24+j
#define NRCOLP 512           // 480 (456 + 24 Jreg cols) padded
#define MLROWS 655           // 3*218 basis rows + 1 ones row
#define MLROWSP 704
#define N2     1368          // kj*3+c
#define N2P    1408
#define KCHUNK (KVP/4)       // 1728, split-K = 4

// ---------------- scratch (__device__ globals: no allocation) ----------------
__device__ float g_Rbuf[KVP*NRCOLP];        // [v][n]
__device__ float g_Lbuf[MLROWSP*KVP];       // [r][v]
__device__ float g_Cpart[4*NRCOLP*MLROWSP]; // split-K partials [s][n][r]
__device__ float g_Gf[NRCOLP*MLROWSP];      // [n][r]
__device__ float g_CPB[NXCOL*N2P];          // [p][n2]
__device__ float g_W2[NUCOL];
__device__ float g_X[BATCH*NXCOL];
__device__ float g_RsB[BATCH*216];          // 24 rotations x 9
__device__ float g_M[BATCH*N2P];

__constant__ int c_par[24] = {-1,0,0,0,1,2,3,4,5,6,7,8,9,9,9,12,13,14,16,17,18,19,20,21};

// ---------------- pack R: columns = jr[v,k]*w[v,j] (456) ++ Jreg[v,j] (24) ----------------
__global__ void build_R_k(const float* __restrict__ Jreg,
                          const float* __restrict__ jr,
                          const float* __restrict__ w) {
    int idx = blockIdx.x*blockDim.x + threadIdx.x;
    if (idx >= KVP*NRCOLP) return;
    int v = idx / NRCOLP, n = idx % NRCOLP;
    float val = 0.f;
    if (v < VNUM) {
        if (n < NUCOL) {
            int k = n / NJ, j = n % NJ;
            val = jr[v*NK + k] * w[v*NJ + j];
        } else if (n < NUCOL + NJ) {
            val = Jreg[v*NJ + (n - NUCOL)];
        }
    }
    g_Rbuf[idx] = val;
}

// ---------------- pack L: row r = c*218+p -> basis[p, v*3+c]; row 654 = ones ----------------
__global__ void build_L_k(const float* __restrict__ vt,
                          const float* __restrict__ sd,
                          const float* __restrict__ pd) {
    int idx = blockIdx.x*blockDim.x + threadIdx.x;
    if (idx >= MLROWSP*KVP) return;
    int r = idx / KVP, v = idx % KVP;
    float val = 0.f;
    if (v < VNUM) {
        if (r < 654) {
            int c = r / 218, p = r % 218;
            if (p == 0)        val = vt[v*3 + c];
            else if (p <= 10)  val = sd[(p-1)*V3CNT + v*3 + c];
            else               val = pd[(p-11)*V3CNT + v*3 + c];
        } else if (r == 654) {
            val = 1.f;
        }
    }
    g_Lbuf[idx] = val;
}

// ---------------- GEMM1: G[n,r] = sum_v Rbuf[v,n] * Lbuf[r,v]; 64x64 tiles, split-K=4 ----------------
__global__ __launch_bounds__(256) void gemm1_k() {
    __shared__ float As[16][68];   // [v][n]
    __shared__ float Bs[16][68];   // [v][r]
    const int r0 = blockIdx.x * 64;
    const int n0 = blockIdx.y * 64;
    const int kBeg = blockIdx.z * KCHUNK;
    const int tid = threadIdx.x;
    const int tx = tid & 15, ty = tid >> 4;
    const int a_v = tid >> 4, a_n = (tid & 15) * 4;
    const int b_r = tid >> 2, b_v = (tid & 3) * 4;
    float acc[4][4] = {{0.f}};

    for (int kt = 0; kt < KCHUNK; kt += 16) {
        int k0 = kBeg + kt;
        float4 av = *(const float4*)(g_Rbuf + (size_t)(k0 + a_v)*NRCOLP + n0 + a_n);
        float4 bv = *(const float4*)(g_Lbuf + (size_t)(r0 + b_r)*KVP + k0 + b_v);
        *(float4*)&As[a_v][a_n] = av;
        Bs[b_v+0][b_r] = bv.x; Bs[b_v+1][b_r] = bv.y;
        Bs[b_v+2][b_r] = bv.z; Bs[b_v+3][b_r] = bv.w;
        __syncthreads();
        #pragma unroll
        for (int kk = 0; kk < 16; ++kk) {
            float4 a  = *(const float4*)&As[kk][ty*4];
            float4 bq = *(const float4*)&Bs[kk][tx*4];
            acc[0][0] += a.x*bq.x; acc[0][1] += a.x*bq.y; acc[0][2] += a.x*bq.z; acc[0][3] += a.x*bq.w;
            acc[1][0] += a.y*bq.x; acc[1][1] += a.y*bq.y; acc[1][2] += a.y*bq.z; acc[1][3] += a.y*bq.w;
            acc[2][0] += a.z*bq.x; acc[2][1] += a.z*bq.y; acc[2][2] += a.z*bq.z; acc[2][3] += a.z*bq.w;
            acc[3][0] += a.w*bq.x; acc[3][1] += a.w*bq.y; acc[3][2] += a.w*bq.z; acc[3][3] += a.w*bq.w;
        }
        __syncthreads();
    }
    float* C = g_Cpart + (size_t)blockIdx.z * NRCOLP * MLROWSP;
    #pragma unroll
    for (int i = 0; i < 4; ++i) {
        int n = n0 + ty*4 + i;
        #pragma unroll
        for (int j = 0; j < 4; ++j)
            C[(size_t)n*MLROWSP + r0 + tx*4 + j] = acc[i][j];
    }
}

__global__ void reduce_k() {
    int i = blockIdx.x*blockDim.x + threadIdx.x;
    const int sz = NRCOLP*MLROWSP;
    if (i >= sz) return;
    g_Gf[i] = g_Cpart[i] + g_Cpart[i+sz] + g_Cpart[i+2*sz] + g_Cpart[i+3*sz];
}

// ---------------- repack G -> CPB[p][n2], extract W2 ----------------
__global__ void repack_k() {
    int idx = blockIdx.x*blockDim.x + threadIdx.x;
    if (idx < NUCOL) g_W2[idx] = g_Gf[idx*MLROWSP + 654];
    if (idx >= NXCOL*N2P) return;
    int p = idx / N2P, n2 = idx % N2P;
    float val = 0.f;
    if (p < 218 && n2 < N2) {
        int kj = n2 / 3, c = n2 % 3;
        val = g_Gf[kj*MLROWSP + c*218 + p];
    }
    g_CPB[idx] = val;
}

// ---------------- per-batch: Rodrigues + feature vector x[b] ----------------
__global__ void build_X_k(const float* __restrict__ beta, const float* __restrict__ theta) {
    int b = blockIdx.x, t = threadIdx.x;
    float* X = g_X + b*NXCOL;
    if (t < 24) {
        float t0 = theta[b*72 + t*3 + 0];
        float t1 = theta[b*72 + t*3 + 1];
        float t2 = theta[b*72 + t*3 + 2];
        float e0 = t0 + 1e-8f, e1 = t1 + 1e-8f, e2 = t2 + 1e-8f;
        float ang  = sqrtf(e0*e0 + e1*e1 + e2*e2);
        float half = 0.5f * ang;
        float sh = sinf(half), w = cosf(half);
        float inva = 1.0f / ang;
        float x = t0*inva*sh, y = t1*inva*sh, z = t2*inva*sh;
        float qn = rsqrtf(w*w + x*x + y*y + z*z);
        w *= qn; x *= qn; y *= qn; z *= qn;
        float R[9];
        R[0] = 1.f - 2.f*(y*y + z*z); R[1] = 2.f*(x*y - w*z);       R[2] = 2.f*(x*z + w*y);
        R[3] = 2.f*(x*y + w*z);       R[4] = 1.f - 2.f*(x*x + z*z); R[5] = 2.f*(y*z - w*x);
        R[6] = 2.f*(x*z - w*y);       R[7] = 2.f*(y*z + w*x);       R[8] = 1.f - 2.f*(x*x + y*y);
        float* rs = g_RsB + b*216 + t*9;
        #pragma unroll
        for (int e = 0; e < 9; ++e) rs[e] = R[e];
        if (t >= 1) {
            float* xp = X + 11 + (t-1)*9;
            #pragma unroll
            for (int e = 0; e < 9; ++e)
                xp[e] = R[e] - ((e==0 || e==4 || e==8) ? 1.f : 0.f);
        }
    }
    if (t == 31) X[0] = 1.f;
    if (t < 10)  X[1 + t] = beta[b*NBETA + t];
    if (t >= 24 && t < 30) X[218 + (t-24)] = 0.f;
}

// ---------------- GEMM2: M[b][n2] = sum_p X[b][p]*CPB[p][n2] ----------------
__global__ __launch_bounds__(256) void gemm2_k() {
    __shared__ float As[16][68];   // [k][m]
    __shared__ float Bs[16][68];   // [k][n]
    const int n0 = blockIdx.x * 64;
    const int m0 = blockIdx.y * 64;
    const int tid = threadIdx.x;
    const int tx = tid & 15, ty = tid >> 4;
    const int am = tid >> 2, ak = (tid & 3) * 4;
    const int bk = tid >> 4, bn = (tid & 15) * 4;
    float acc[4][4] = {{0.f}};

    for (int k0 = 0; k0 < NXCOL; k0 += 16) {
        float4 av = *(const float4*)(g_X   + (size_t)(m0 + am)*NXCOL + k0 + ak);
        float4 bv = *(const float4*)(g_CPB + (size_t)(k0 + bk)*N2P  + n0 + bn);
        As[ak+0][am] = av.x; As[ak+1][am] = av.y;
        As[ak+2][am] = av.z; As[ak+3][am] = av.w;
        *(float4*)&Bs[bk][bn] = bv;
        __syncthreads();
        #pragma unroll
        for (int kk = 0; kk < 16; ++kk) {
            float4 a  = *(const float4*)&As[kk][ty*4];
            float4 bq = *(const float4*)&Bs[kk][tx*4];
            acc[0][0] += a.x*bq.x; acc[0][1] += a.x*bq.y; acc[0][2] += a.x*bq.z; acc[0][3] += a.x*bq.w;
            acc[1][0] += a.y*bq.x; acc[1][1] += a.y*bq.y; acc[1][2] += a.y*bq.z; acc[1][3] += a.y*bq.w;
            acc[2][0] += a.z*bq.x; acc[2][1] += a.z*bq.y; acc[2][2] += a.z*bq.z; acc[2][3] += a.z*bq.w;
            acc[3][0] += a.w*bq.x; acc[3][1] += a.w*bq.y; acc[3][2] += a.w*bq.z; acc[3][3] += a.w*bq.w;
        }
        __syncthreads();
    }
    #pragma unroll
    for (int i = 0; i < 4; ++i) {
        int m = m0 + ty*4 + i;
        #pragma unroll
        for (int j = 0; j < 4; ++j)
            g_M[(size_t)m*N2P + n0 + tx*4 + j] = acc[i][j];
    }
}

// ---------------- final: J, kinematic chain A, joints ----------------
__global__ void final_k(const float* __restrict__ beta,
                        const float* __restrict__ trans,
                        float* __restrict__ out) {
    __shared__ float sRs[216], sJ[72], sRes[288], sW2[456], sBeta[10], sTr[3];
    int b = blockIdx.x, t = threadIdx.x;  // 128 threads
    for (int i = t; i < 216; i += 128) sRs[i] = g_RsB[b*216 + i];
    for (int i = t; i < 456; i += 128) sW2[i] = g_W2[i];
    if (t < 10) sBeta[t] = beta[b*NBETA + t];
    if (t < 3)  sTr[t]   = trans[b*3 + t];
    __syncthreads();

    // J[j][c] = G[456+j][c*218+0] + sum beta*G[..][c*218+1+nb]
    if (t < 72) {
        int j = t / 3, c = t % 3;
        const float* g = g_Gf + (456 + j)*MLROWSP + c*218;
        float acc = g[0];
        #pragma unroll
        for (int nb = 0; nb < 10; ++nb) acc += sBeta[nb]*g[1 + nb];
        sJ[j*3 + c] = acc;
    }
    __syncthreads();

    // kinematic chain (serial, one thread; 7 blocks/SM hide it)
    if (t == 0) {
        for (int r = 0; r < 3; ++r) {          // root: Rs0 @ diag(1,-1,-1) | J0
            sRes[r*4+0] =  sRs[r*3+0];
            sRes[r*4+1] = -sRs[r*3+1];
            sRes[r*4+2] = -sRs[r*3+2];
            sRes[r*4+3] =  sJ[r];
        }
        for (int i = 1; i < 24; ++i) {
            int p = c_par[i];
            float t0 = sJ[i*3+0] - sJ[p*3+0];
            float t1 = sJ[i*3+1] - sJ[p*3+1];
            float t2 = sJ[i*3+2] - sJ[p*3+2];
            const float* Ri = sRs + i*9;
            const float* rp = sRes + p*12;
            float* ro = sRes + i*12;
            for (int r = 0; r < 3; ++r) {
                float p0 = rp[r*4+0], p1 = rp[r*4+1], p2 = rp[r*4+2], p3 = rp[r*4+3];
                ro[r*4+0] = p0*Ri[0] + p1*Ri[3] + p2*Ri[6];
                ro[r*4+1] = p0*Ri[1] + p1*Ri[4] + p2*Ri[7];
                ro[r*4+2] = p0*Ri[2] + p1*Ri[5] + p2*Ri[8];
                ro[r*4+3] = p0*t0 + p1*t1 + p2*t2 + p3;
            }
        }
    }
    __syncthreads();

    // A[..,3] -= res[..,:3] . J   (each thread touches only its own slot)
    if (t < 72) {
        int j = t / 3, r = t % 3;
        float* ro = sRes + j*12 + r*4;
        float d = ro[0]*sJ[j*3+0] + ro[1]*sJ[j*3+1] + ro[2]*sJ[j*3+2];
        ro[3] -= d;
    }
    __syncthreads();

    // joints[k][r] = trans[r] + sum_j A[j,r,:3].m[k,j,:] + A[j,r,3]*W2[k,j]
    if (t < 57) {
        int k = t / 3, r = t % 3;
        float acc = sTr[r];
        const float* Mb = g_M + (size_t)b*N2P;
        #pragma unroll
        for (int j = 0; j < 24; ++j) {
            int kj = k*24 + j;
            const float* m = Mb + kj*3;
            const float* a = sRes + j*12 + r*4;
            acc += a[0]*m[0] + a[1]*m[1] + a[2]*m[2] + a[3]*sW2[kj];
        }
        out[b*57 + t] = acc;
    }
}

// ---------------- launcher ----------------
extern "C" void kernel_launch(void* const* d_in, const int* in_sizes, int n_in,
                              void* d_out, int out_size) {
    const float* beta  = (const float*)d_in[0];
    const float* theta = (const float*)d_in[1];
    const float* trans = (const float*)d_in[2];
    const float* vt    = (const float*)d_in[3];
    const float* sd    = (const float*)d_in[4];
    const float* Jreg  = (const float*)d_in[5];
    const float* pd    = (const float*)d_in[6];
    const float* jr    = (const float*)d_in[7];
    const float* w     = (const float*)d_in[8];
    float* out = (float*)d_out;

    build_R_k<<<(KVP*NRCOLP + 255)/256, 256>>>(Jreg, jr, w);
    build_L_k<<<(MLROWSP*KVP + 255)/256, 256>>>(vt, sd, pd);
    gemm1_k<<<dim3(MLROWSP/64, NRCOLP/64, 4), 256>>>();
    reduce_k<<<(NRCOLP*MLROWSP + 255)/256, 256>>>();
    repack_k<<<(NXCOL*N2P + 255)/256, 256>>>();
    build_X_k<<<BATCH, 32>>>(beta, theta);
    gemm2_k<<<dim3(N2P/64, BATCH/64), 256>>>();
    final_k<<<BATCH, 128>>>(beta, trans, out);
}